// round 5
// baseline (speedup 1.0000x reference)
#include <cuda_runtime.h>
#include <cstdint>

#define N_NODES 100000
#define N_EDGES 3200000

// ---------------- device scratch (static globals; allocation-free) ----------
__device__ int   g_is64;
__device__ int   g_deg[N_NODES];
__device__ int   g_fill[N_NODES];
__device__ float g_dinv[N_NODES];
__device__ int   g_rowptr[N_NODES + 1];
__device__ int   g_col[N_EDGES];
__device__ __align__(16) float g_wgt[N_EDGES];
__device__ __align__(16) float g_bufA[(size_t)N_NODES * 128];
__device__ __align__(16) float g_bufB[(size_t)N_NODES * 128];
__device__ __align__(16) float g_h3[(size_t)N_NODES * 512];
__device__ __align__(16) float g_h4[(size_t)N_NODES * 512];

// Resolve scratch buffers in DEVICE code only (no host symbol-address queries).
__device__ __forceinline__ float* get_buf(int id) {
    switch (id) {
        case 0: return g_bufA;
        case 1: return g_bufB;
        case 2: return g_h3;
        default: return g_h4;
    }
}

// Edge index may arrive as int32 (harness dtype set) or int64 (reference decl).
__device__ __forceinline__ int edge_at(const void* __restrict__ ei, size_t i) {
    if (g_is64) return (int)((const long long*)ei)[i];
    return ((const int*)ei)[i];
}

// Detect dtype: if the first 256 entries, viewed as int64, are all valid node
// ids, the buffer is int64. (int32 data viewed as int64 packs two random node
// ids -> value >= 2^32 with prob ~1-1e-5 per entry.)
__global__ void k_detect(const void* __restrict__ ei) {
    if (threadIdx.x == 0 && blockIdx.x == 0) {
        const long long* p = (const long long*)ei;
        int ok = 1;
        for (int i = 0; i < 256; i++) {
            long long v = p[i];
            if (v < 0 || v >= N_NODES) { ok = 0; break; }
        }
        g_is64 = ok;
    }
}

// ---------------- graph preprocessing ---------------------------------------
__global__ void k_init() {
    int i = blockIdx.x * blockDim.x + threadIdx.x;
    if (i < N_NODES) { g_deg[i] = 1; g_fill[i] = 0; }   // deg starts at 1 (self loop)
}

__global__ void k_count(const void* __restrict__ ei) {
    int e = blockIdx.x * blockDim.x + threadIdx.x;
    if (e < N_EDGES) {
        int d = edge_at(ei, (size_t)N_EDGES + e);
        atomicAdd(&g_deg[d], 1);
    }
}

__global__ void k_dinv() {
    int i = blockIdx.x * blockDim.x + threadIdx.x;
    if (i < N_NODES) g_dinv[i] = rsqrtf((float)g_deg[i]);
}

// single-block exclusive scan of (deg-1) -> rowptr
__global__ void k_scan() {
    __shared__ int warp_sums[32];
    __shared__ int s_carry;
    const int BS = 1024;
    int tid = threadIdx.x, lane = tid & 31, wid = tid >> 5;
    if (tid == 0) { s_carry = 0; g_rowptr[0] = 0; }
    __syncthreads();
    for (int base = 0; base < N_NODES; base += BS) {
        int i = base + tid;
        int v = (i < N_NODES) ? (g_deg[i] - 1) : 0;
        int x = v;
        #pragma unroll
        for (int o = 1; o < 32; o <<= 1) {
            int n = __shfl_up_sync(0xffffffffu, x, o);
            if (lane >= o) x += n;
        }
        if (lane == 31) warp_sums[wid] = x;
        __syncthreads();
        if (wid == 0) {
            int s = warp_sums[lane];
            #pragma unroll
            for (int o = 1; o < 32; o <<= 1) {
                int n = __shfl_up_sync(0xffffffffu, s, o);
                if (lane >= o) s += n;
            }
            warp_sums[lane] = s;
        }
        __syncthreads();
        int warp_off = (wid > 0) ? warp_sums[wid - 1] : 0;
        int incl = x + warp_off + s_carry;
        if (i < N_NODES) g_rowptr[i + 1] = incl;
        __syncthreads();
        if (tid == BS - 1) s_carry = incl;
        __syncthreads();
    }
}

__global__ void k_fill(const void* __restrict__ ei) {
    int e = blockIdx.x * blockDim.x + threadIdx.x;
    if (e < N_EDGES) {
        int s = edge_at(ei, e);
        int d = edge_at(ei, (size_t)N_EDGES + e);
        int p = g_rowptr[d] + atomicAdd(&g_fill[d], 1);
        g_col[p] = s;
        g_wgt[p] = g_dinv[s] * g_dinv[d];
    }
}

// ---------------- aggregation: one warp per node, 128 features ---------------
template<bool BIAS, bool RELU>
__global__ void k_aggregate(int in_id, int out_id, const float* __restrict__ bias) {
    const float* hin = get_buf(in_id);
    float* hout = get_buf(out_id);
    int lane = threadIdx.x & 31;
    int node = blockIdx.x * (blockDim.x >> 5) + (threadIdx.x >> 5);
    if (node >= N_NODES) return;

    float dv = g_dinv[node];
    float4 acc = ((const float4*)(hin + (size_t)node * 128))[lane];
    float sw = dv * dv;
    acc.x *= sw; acc.y *= sw; acc.z *= sw; acc.w *= sw;

    int e = g_rowptr[node];
    int end = g_rowptr[node + 1];
    for (; e + 2 <= end; e += 2) {
        int s0 = __ldg(&g_col[e]);
        int s1 = __ldg(&g_col[e + 1]);
        float w0 = __ldg(&g_wgt[e]);
        float w1 = __ldg(&g_wgt[e + 1]);
        float4 v0 = ((const float4*)(hin + (size_t)s0 * 128))[lane];
        float4 v1 = ((const float4*)(hin + (size_t)s1 * 128))[lane];
        acc.x += v0.x * w0; acc.y += v0.y * w0; acc.z += v0.z * w0; acc.w += v0.w * w0;
        acc.x += v1.x * w1; acc.y += v1.y * w1; acc.z += v1.z * w1; acc.w += v1.w * w1;
    }
    if (e < end) {
        int s0 = __ldg(&g_col[e]);
        float w0 = __ldg(&g_wgt[e]);
        float4 v0 = ((const float4*)(hin + (size_t)s0 * 128))[lane];
        acc.x += v0.x * w0; acc.y += v0.y * w0; acc.z += v0.z * w0; acc.w += v0.w * w0;
    }
    if (BIAS) {
        float4 b4 = ((const float4*)bias)[lane];
        acc.x += b4.x; acc.y += b4.y; acc.z += b4.z; acc.w += b4.w;
    }
    if (RELU) {
        acc.x = fmaxf(acc.x, 0.f); acc.y = fmaxf(acc.y, 0.f);
        acc.z = fmaxf(acc.z, 0.f); acc.w = fmaxf(acc.w, 0.f);
    }
    ((float4*)(hout + (size_t)node * 128))[lane] = acc;
}

// ---------------- SGEMM: C[M,N] = A[M,K] @ B[K,N] (+bias)(+relu) -------------
// BM=128, BN=128, BK=8, TM=TN=8, 256 threads. Requires N%128==0, K%8==0.
template<bool BIAS, bool RELU>
__global__ __launch_bounds__(256, 2)
void k_sgemm(int M, int N, int K,
             const float* __restrict__ Aext, int Aid,
             const float* __restrict__ B,
             const float* __restrict__ bias, int Cid) {
    constexpr int BM = 128, BN = 128, BK = 8, TM = 8, TN = 8;
    const float* A = (Aid >= 0) ? get_buf(Aid) : Aext;
    float* C = get_buf(Cid);
    __shared__ float As[BK][BM];
    __shared__ float Bs[BK][BN];
    int tid = threadIdx.x;
    int cCol = blockIdx.x, cRow = blockIdx.y;
    int threadCol = tid % (BN / TN);          // 0..15
    int threadRow = tid / (BN / TN);          // 0..15
    int innerRowA = tid / (BK / 4);           // 0..127
    int innerColA = tid % (BK / 4);           // 0..1 (x4 floats)
    int innerRowB = tid / (BN / 4);           // 0..7
    int innerColB = tid % (BN / 4);           // 0..31 (x4 floats)

    const float* Ab = A + (size_t)cRow * BM * K;
    const float* Bb = B + cCol * BN;
    int rowA = cRow * BM + innerRowA;
    bool rowAok = rowA < M;

    float acc[TM][TN];
    #pragma unroll
    for (int i = 0; i < TM; i++)
        #pragma unroll
        for (int j = 0; j < TN; j++) acc[i][j] = 0.f;

    for (int k0 = 0; k0 < K; k0 += BK) {
        float4 a4 = rowAok
            ? *(const float4*)(Ab + (size_t)innerRowA * K + k0 + innerColA * 4)
            : make_float4(0.f, 0.f, 0.f, 0.f);
        As[innerColA * 4 + 0][innerRowA] = a4.x;
        As[innerColA * 4 + 1][innerRowA] = a4.y;
        As[innerColA * 4 + 2][innerRowA] = a4.z;
        As[innerColA * 4 + 3][innerRowA] = a4.w;
        *(float4*)&Bs[innerRowB][innerColB * 4] =
            *(const float4*)(Bb + (size_t)(k0 + innerRowB) * N + innerColB * 4);
        __syncthreads();
        #pragma unroll
        for (int k = 0; k < BK; k++) {
            float regM[TM], regN[TN];
            *(float4*)&regM[0] = *(float4*)&As[k][threadRow * TM];
            *(float4*)&regM[4] = *(float4*)&As[k][threadRow * TM + 4];
            *(float4*)&regN[0] = *(float4*)&Bs[k][threadCol * TN];
            *(float4*)&regN[4] = *(float4*)&Bs[k][threadCol * TN + 4];
            #pragma unroll
            for (int i = 0; i < TM; i++)
                #pragma unroll
                for (int j = 0; j < TN; j++)
                    acc[i][j] += regM[i] * regN[j];
        }
        __syncthreads();
    }

    float bv[TN];
    if (BIAS) {
        #pragma unroll
        for (int j = 0; j < TN; j++)
            bv[j] = bias[cCol * BN + threadCol * TN + j];
    }
    #pragma unroll
    for (int i = 0; i < TM; i++) {
        int row = cRow * BM + threadRow * TM + i;
        if (row >= M) continue;
        float* Crow = C + (size_t)row * N + cCol * BN + threadCol * TN;
        #pragma unroll
        for (int j = 0; j < TN; j += 4) {
            float4 v;
            v.x = acc[i][j + 0] + (BIAS ? bv[j + 0] : 0.f);
            v.y = acc[i][j + 1] + (BIAS ? bv[j + 1] : 0.f);
            v.z = acc[i][j + 2] + (BIAS ? bv[j + 2] : 0.f);
            v.w = acc[i][j + 3] + (BIAS ? bv[j + 3] : 0.f);
            if (RELU) {
                v.x = fmaxf(v.x, 0.f); v.y = fmaxf(v.y, 0.f);
                v.z = fmaxf(v.z, 0.f); v.w = fmaxf(v.w, 0.f);
            }
            *(float4*)&Crow[j] = v;
        }
    }
}

// ---------------- classification head: out = h4 @ Wc + bc (N=3) --------------
__global__ void k_final(const float* __restrict__ Wc,
                        const float* __restrict__ bc, float* __restrict__ out) {
    const float* h4 = g_h4;
    __shared__ float sW[512 * 3];
    int tid = threadIdx.x;
    for (int i = tid; i < 512 * 3; i += blockDim.x) sW[i] = Wc[i];
    __syncthreads();
    int lane = tid & 31, wid = tid >> 5;
    int node = blockIdx.x * (blockDim.x >> 5) + wid;
    if (node >= N_NODES) return;
    const float* row = h4 + (size_t)node * 512;
    float a0 = 0.f, a1 = 0.f, a2 = 0.f;
    #pragma unroll
    for (int kk = 0; kk < 16; kk++) {
        int k = kk * 32 + lane;
        float v = row[k];
        a0 += v * sW[k * 3 + 0];
        a1 += v * sW[k * 3 + 1];
        a2 += v * sW[k * 3 + 2];
    }
    #pragma unroll
    for (int o = 16; o > 0; o >>= 1) {
        a0 += __shfl_down_sync(0xffffffffu, a0, o);
        a1 += __shfl_down_sync(0xffffffffu, a1, o);
        a2 += __shfl_down_sync(0xffffffffu, a2, o);
    }
    if (lane == 0) {
        out[(size_t)node * 3 + 0] = a0 + bc[0];
        out[(size_t)node * 3 + 1] = a1 + bc[1];
        out[(size_t)node * 3 + 2] = a2 + bc[2];
    }
}

// ---------------- launch -----------------------------------------------------
extern "C" void kernel_launch(void* const* d_in, const int* in_sizes, int n_in,
                              void* d_out, int out_size) {
    const float* x  = (const float*)d_in[0];
    const void*  ei = d_in[1];                 // int32 or int64, auto-detected
    const float* W1 = (const float*)d_in[2];
    const float* b1 = (const float*)d_in[3];
    const float* W2 = (const float*)d_in[4];
    const float* b2 = (const float*)d_in[5];
    const float* W3 = (const float*)d_in[6];
    const float* b3 = (const float*)d_in[7];
    const float* Wi = (const float*)d_in[8];
    const float* bi = (const float*)d_in[9];
    const float* Wc = (const float*)d_in[10];
    const float* bc = (const float*)d_in[11];
    float* out = (float*)d_out;

    // buffer ids: 0 = g_bufA, 1 = g_bufB, 2 = g_h3, 3 = g_h4
    const int NB_NODE = (N_NODES + 255) / 256;        // 391
    const int NB_EDGE = (N_EDGES + 255) / 256;        // 12500
    const int NB_AGG  = (N_NODES + 7) / 8;            // 12500 (8 warps/block)
    const dim3 GEMM_GRID_128(1, (N_NODES + 127) / 128);
    const dim3 GEMM_GRID_512(4, (N_NODES + 127) / 128);

    // graph structure (identical for all convs)
    k_detect<<<1, 32>>>(ei);
    k_init<<<NB_NODE, 256>>>();
    k_count<<<NB_EDGE, 256>>>(ei);
    k_dinv<<<NB_NODE, 256>>>();
    k_scan<<<1, 1024>>>();
    k_fill<<<NB_EDGE, 256>>>(ei);

    // conv1: h1 = relu(Â(x@W1) + b1)
    k_sgemm<false, false><<<GEMM_GRID_128, 256>>>(N_NODES, 128, 128, x, -1, W1, nullptr, 0);
    k_aggregate<true, true><<<NB_AGG, 256>>>(0, 1, b1);

    // conv2: h2 = relu(Â(h1@W2) + b2)
    k_sgemm<false, false><<<GEMM_GRID_128, 256>>>(N_NODES, 128, 128, nullptr, 1, W2, nullptr, 0);
    k_aggregate<true, true><<<NB_AGG, 256>>>(0, 1, b2);

    // conv3: h3 = relu((Âh2)@W3 + b3)  -- aggregate at 128-dim, THEN expand to 512
    k_aggregate<false, false><<<NB_AGG, 256>>>(1, 0, nullptr);
    k_sgemm<true, true><<<GEMM_GRID_512, 256>>>(N_NODES, 512, 128, nullptr, 0, W3, b3, 2);

    // MLP: h4 = relu(h3@Wi + bi); out = h4@Wc + bc
    k_sgemm<true, true><<<GEMM_GRID_512, 256>>>(N_NODES, 512, 512, nullptr, 2, Wi, bi, 3);
    k_final<<<NB_AGG, 256>>>(Wc, bc, out);
}

// round 7
// speedup vs baseline: 1.8140x; 1.8140x over previous
#include <cuda_runtime.h>
#include <cstdint>

#define N_NODES 100000
#define N_EDGES 3200000

// ---------------- device scratch (static globals; allocation-free) ----------
__device__ int   g_is64;
__device__ int   g_deg[N_NODES];
__device__ int   g_fill[N_NODES];
__device__ float g_dinv[N_NODES];
__device__ int   g_rowptr[N_NODES + 1];
__device__ int   g_col[N_EDGES];
__device__ __align__(16) float g_wgt[N_EDGES];
__device__ __align__(16) float g_bufA[(size_t)N_NODES * 128];
__device__ __align__(16) float g_bufB[(size_t)N_NODES * 128];
__device__ __align__(16) float g_h3[(size_t)N_NODES * 512];
__device__ __align__(16) float g_h4[(size_t)N_NODES * 512];

// Resolve scratch buffers in DEVICE code only (no host symbol-address queries).
__device__ __forceinline__ float* get_buf(int id) {
    switch (id) {
        case 0: return g_bufA;
        case 1: return g_bufB;
        case 2: return g_h3;
        default: return g_h4;
    }
}

// Edge index may arrive as int32 (harness dtype set) or int64 (reference decl).
__device__ __forceinline__ int edge_at(const void* __restrict__ ei, size_t i) {
    if (g_is64) return (int)((const long long*)ei)[i];
    return ((const int*)ei)[i];
}

__global__ void k_detect(const void* __restrict__ ei) {
    if (threadIdx.x == 0 && blockIdx.x == 0) {
        const long long* p = (const long long*)ei;
        int ok = 1;
        for (int i = 0; i < 256; i++) {
            long long v = p[i];
            if (v < 0 || v >= N_NODES) { ok = 0; break; }
        }
        g_is64 = ok;
    }
}

// ---------------- graph preprocessing ---------------------------------------
__global__ void k_init() {
    int i = blockIdx.x * blockDim.x + threadIdx.x;
    if (i < N_NODES) { g_deg[i] = 1; g_fill[i] = 0; }   // deg starts at 1 (self loop)
}

__global__ void k_count(const void* __restrict__ ei) {
    int e = blockIdx.x * blockDim.x + threadIdx.x;
    if (e < N_EDGES) {
        int d = edge_at(ei, (size_t)N_EDGES + e);
        atomicAdd(&g_deg[d], 1);
    }
}

__global__ void k_dinv() {
    int i = blockIdx.x * blockDim.x + threadIdx.x;
    if (i < N_NODES) g_dinv[i] = rsqrtf((float)g_deg[i]);
}

// single-block exclusive scan of (deg-1) -> rowptr
__global__ void k_scan() {
    __shared__ int warp_sums[32];
    __shared__ int s_carry;
    const int BS = 1024;
    int tid = threadIdx.x, lane = tid & 31, wid = tid >> 5;
    if (tid == 0) { s_carry = 0; g_rowptr[0] = 0; }
    __syncthreads();
    for (int base = 0; base < N_NODES; base += BS) {
        int i = base + tid;
        int v = (i < N_NODES) ? (g_deg[i] - 1) : 0;
        int x = v;
        #pragma unroll
        for (int o = 1; o < 32; o <<= 1) {
            int n = __shfl_up_sync(0xffffffffu, x, o);
            if (lane >= o) x += n;
        }
        if (lane == 31) warp_sums[wid] = x;
        __syncthreads();
        if (wid == 0) {
            int s = warp_sums[lane];
            #pragma unroll
            for (int o = 1; o < 32; o <<= 1) {
                int n = __shfl_up_sync(0xffffffffu, s, o);
                if (lane >= o) s += n;
            }
            warp_sums[lane] = s;
        }
        __syncthreads();
        int warp_off = (wid > 0) ? warp_sums[wid - 1] : 0;
        int incl = x + warp_off + s_carry;
        if (i < N_NODES) g_rowptr[i + 1] = incl;
        __syncthreads();
        if (tid == BS - 1) s_carry = incl;
        __syncthreads();
    }
}

__global__ void k_fill(const void* __restrict__ ei) {
    int e = blockIdx.x * blockDim.x + threadIdx.x;
    if (e < N_EDGES) {
        int s = edge_at(ei, e);
        int d = edge_at(ei, (size_t)N_EDGES + e);
        int p = g_rowptr[d] + atomicAdd(&g_fill[d], 1);
        g_col[p] = s;
        g_wgt[p] = g_dinv[s] * g_dinv[d];
    }
}

// ---------------- aggregation: one warp per node, 128 features ---------------
template<bool BIAS, bool RELU>
__global__ void k_aggregate(int in_id, int out_id, const float* __restrict__ bias) {
    const float* hin = get_buf(in_id);
    float* hout = get_buf(out_id);
    int lane = threadIdx.x & 31;
    int node = blockIdx.x * (blockDim.x >> 5) + (threadIdx.x >> 5);
    if (node >= N_NODES) return;

    float dv = g_dinv[node];
    float4 acc = ((const float4*)(hin + (size_t)node * 128))[lane];
    float sw = dv * dv;
    acc.x *= sw; acc.y *= sw; acc.z *= sw; acc.w *= sw;

    int e = g_rowptr[node];
    int end = g_rowptr[node + 1];
    for (; e + 2 <= end; e += 2) {
        int s0 = __ldg(&g_col[e]);
        int s1 = __ldg(&g_col[e + 1]);
        float w0 = __ldg(&g_wgt[e]);
        float w1 = __ldg(&g_wgt[e + 1]);
        float4 v0 = ((const float4*)(hin + (size_t)s0 * 128))[lane];
        float4 v1 = ((const float4*)(hin + (size_t)s1 * 128))[lane];
        acc.x += v0.x * w0; acc.y += v0.y * w0; acc.z += v0.z * w0; acc.w += v0.w * w0;
        acc.x += v1.x * w1; acc.y += v1.y * w1; acc.z += v1.z * w1; acc.w += v1.w * w1;
    }
    if (e < end) {
        int s0 = __ldg(&g_col[e]);
        float w0 = __ldg(&g_wgt[e]);
        float4 v0 = ((const float4*)(hin + (size_t)s0 * 128))[lane];
        acc.x += v0.x * w0; acc.y += v0.y * w0; acc.z += v0.z * w0; acc.w += v0.w * w0;
    }
    if (BIAS) {
        float4 b4 = ((const float4*)bias)[lane];
        acc.x += b4.x; acc.y += b4.y; acc.z += b4.z; acc.w += b4.w;
    }
    if (RELU) {
        acc.x = fmaxf(acc.x, 0.f); acc.y = fmaxf(acc.y, 0.f);
        acc.z = fmaxf(acc.z, 0.f); acc.w = fmaxf(acc.w, 0.f);
    }
    ((float4*)(hout + (size_t)node * 128))[lane] = acc;
}

// ---------------- TF32 tensor-core GEMM --------------------------------------
// C[M,N] = A[M,K] @ B[K,N] (+bias)(+relu), fp32 in/out, tf32 mma, fp32 accum.
// BM=BN=128, BK=32, 256 threads = 8 warps (4 row x 2 col), warp tile 32x64.
// mma.sync.aligned.m16n8k8.row.col.f32.tf32.tf32.f32
__device__ __forceinline__ uint32_t f2tf32(float f) {
    uint32_t u;
    asm("cvt.rna.tf32.f32 %0, %1;" : "=r"(u) : "f"(f));
    return u;
}

template<bool BIAS, bool RELU>
__global__ __launch_bounds__(256, 2)
void k_tf32gemm(int M, int N, int K,
                const float* __restrict__ Aext, int Aid,
                const float* __restrict__ B,
                const float* __restrict__ bias, int Cid) {
    constexpr int BM = 128, BN = 128, BK = 32;
    const float* A = (Aid >= 0) ? get_buf(Aid) : Aext;
    float* C = get_buf(Cid);

    __shared__ uint32_t As[BK][BM + 4];   // k-major
    __shared__ uint32_t Bs[BK][BN + 4];   // k-major

    const int tid = threadIdx.x;
    const int w = tid >> 5;
    const int lane = tid & 31;
    const int groupID = lane >> 2;        // 0..7
    const int tig = lane & 3;             // 0..3
    const int warp_m = (w & 3) * 32;      // 0,32,64,96
    const int warp_n = (w >> 2) * 64;     // 0,64

    const int block_m = blockIdx.y * BM;
    const int n0 = blockIdx.x * BN;

    float c[2][8][4];
    #pragma unroll
    for (int i = 0; i < 2; i++)
        #pragma unroll
        for (int j = 0; j < 8; j++)
            #pragma unroll
            for (int r = 0; r < 4; r++) c[i][j][r] = 0.f;

    // global-load assignments
    const int arow = tid >> 3;            // 0..31 (+32*it)
    const int akq  = (tid & 7) * 4;       // 0,4,...,28
    const int bkr  = tid >> 5;            // 0..7 (+8*it)
    const int bc4  = (tid & 31) * 4;      // 0..124

    for (int k0 = 0; k0 < K; k0 += BK) {
        // load A tile (transpose to k-major, cvt tf32)
        #pragma unroll
        for (int it = 0; it < 4; it++) {
            int r = arow + it * 32;
            int gr = block_m + r;
            float4 a4 = (gr < M)
                ? *(const float4*)(A + (size_t)gr * K + k0 + akq)
                : make_float4(0.f, 0.f, 0.f, 0.f);
            As[akq + 0][r] = f2tf32(a4.x);
            As[akq + 1][r] = f2tf32(a4.y);
            As[akq + 2][r] = f2tf32(a4.z);
            As[akq + 3][r] = f2tf32(a4.w);
        }
        // load B tile (natural k-major, cvt tf32)
        #pragma unroll
        for (int it = 0; it < 4; it++) {
            int kr = bkr + it * 8;
            float4 b4 = *(const float4*)(B + (size_t)(k0 + kr) * N + n0 + bc4);
            Bs[kr][bc4 + 0] = f2tf32(b4.x);
            Bs[kr][bc4 + 1] = f2tf32(b4.y);
            Bs[kr][bc4 + 2] = f2tf32(b4.z);
            Bs[kr][bc4 + 3] = f2tf32(b4.w);
        }
        __syncthreads();

        #pragma unroll
        for (int ks = 0; ks < BK / 8; ks++) {
            const int kb = ks * 8;
            uint32_t af[2][4];
            #pragma unroll
            for (int mt = 0; mt < 2; mt++) {
                int m0 = warp_m + mt * 16;
                af[mt][0] = As[kb + tig    ][m0 + groupID];
                af[mt][1] = As[kb + tig    ][m0 + groupID + 8];
                af[mt][2] = As[kb + tig + 4][m0 + groupID];
                af[mt][3] = As[kb + tig + 4][m0 + groupID + 8];
            }
            uint32_t bf[8][2];
            #pragma unroll
            for (int nt = 0; nt < 8; nt++) {
                int nb = warp_n + nt * 8;
                bf[nt][0] = Bs[kb + tig    ][nb + groupID];
                bf[nt][1] = Bs[kb + tig + 4][nb + groupID];
            }
            #pragma unroll
            for (int mt = 0; mt < 2; mt++)
                #pragma unroll
                for (int nt = 0; nt < 8; nt++) {
                    asm volatile(
                        "mma.sync.aligned.m16n8k8.row.col.f32.tf32.tf32.f32 "
                        "{%0,%1,%2,%3}, {%4,%5,%6,%7}, {%8,%9}, {%0,%1,%2,%3};\n"
                        : "+f"(c[mt][nt][0]), "+f"(c[mt][nt][1]),
                          "+f"(c[mt][nt][2]), "+f"(c[mt][nt][3])
                        : "r"(af[mt][0]), "r"(af[mt][1]), "r"(af[mt][2]), "r"(af[mt][3]),
                          "r"(bf[nt][0]), "r"(bf[nt][1]));
                }
        }
        __syncthreads();
    }

    // epilogue: bias + relu + guarded float2 stores
    #pragma unroll
    for (int nt = 0; nt < 8; nt++) {
        int col = n0 + warp_n + nt * 8 + 2 * tig;
        float b0 = 0.f, b1 = 0.f;
        if (BIAS) { b0 = bias[col]; b1 = bias[col + 1]; }
        #pragma unroll
        for (int mt = 0; mt < 2; mt++) {
            int rbase = block_m + warp_m + mt * 16 + groupID;
            float v0 = c[mt][nt][0] + b0;
            float v1 = c[mt][nt][1] + b1;
            float v2 = c[mt][nt][2] + b0;
            float v3 = c[mt][nt][3] + b1;
            if (RELU) {
                v0 = fmaxf(v0, 0.f); v1 = fmaxf(v1, 0.f);
                v2 = fmaxf(v2, 0.f); v3 = fmaxf(v3, 0.f);
            }
            if (rbase < M)
                *(float2*)(C + (size_t)rbase * N + col) = make_float2(v0, v1);
            if (rbase + 8 < M)
                *(float2*)(C + (size_t)(rbase + 8) * N + col) = make_float2(v2, v3);
        }
    }
}

// ---------------- classification head: out = h4 @ Wc + bc (N=3) --------------
__global__ void k_final(const float* __restrict__ Wc,
                        const float* __restrict__ bc, float* __restrict__ out) {
    const float* h4 = g_h4;
    __shared__ float sW[512 * 3];
    int tid = threadIdx.x;
    for (int i = tid; i < 512 * 3; i += blockDim.x) sW[i] = Wc[i];
    __syncthreads();
    int lane = tid & 31, wid = tid >> 5;
    int node = blockIdx.x * (blockDim.x >> 5) + wid;
    if (node >= N_NODES) return;
    const float* row = h4 + (size_t)node * 512;
    float a0 = 0.f, a1 = 0.f, a2 = 0.f;
    #pragma unroll
    for (int kk = 0; kk < 16; kk++) {
        int k = kk * 32 + lane;
        float v = row[k];
        a0 += v * sW[k * 3 + 0];
        a1 += v * sW[k * 3 + 1];
        a2 += v * sW[k * 3 + 2];
    }
    #pragma unroll
    for (int o = 16; o > 0; o >>= 1) {
        a0 += __shfl_down_sync(0xffffffffu, a0, o);
        a1 += __shfl_down_sync(0xffffffffu, a1, o);
        a2 += __shfl_down_sync(0xffffffffu, a2, o);
    }
    if (lane == 0) {
        out[(size_t)node * 3 + 0] = a0 + bc[0];
        out[(size_t)node * 3 + 1] = a1 + bc[1];
        out[(size_t)node * 3 + 2] = a2 + bc[2];
    }
}

// ---------------- launch -----------------------------------------------------
extern "C" void kernel_launch(void* const* d_in, const int* in_sizes, int n_in,
                              void* d_out, int out_size) {
    const float* x  = (const float*)d_in[0];
    const void*  ei = d_in[1];                 // int32 or int64, auto-detected
    const float* W1 = (const float*)d_in[2];
    const float* b1 = (const float*)d_in[3];
    const float* W2 = (const float*)d_in[4];
    const float* b2 = (const float*)d_in[5];
    const float* W3 = (const float*)d_in[6];
    const float* b3 = (const float*)d_in[7];
    const float* Wi = (const float*)d_in[8];
    const float* bi = (const float*)d_in[9];
    const float* Wc = (const float*)d_in[10];
    const float* bc = (const float*)d_in[11];
    float* out = (float*)d_out;

    // buffer ids: 0 = g_bufA, 1 = g_bufB, 2 = g_h3, 3 = g_h4
    const int NB_NODE = (N_NODES + 255) / 256;        // 391
    const int NB_EDGE = (N_EDGES + 255) / 256;        // 12500
    const int NB_AGG  = (N_NODES + 7) / 8;            // 12500 (8 warps/block)
    const dim3 GRID_128(1, (N_NODES + 127) / 128);    // 782 rows
    const dim3 GRID_512(4, (N_NODES + 127) / 128);

    // graph structure (identical for all convs)
    k_detect<<<1, 32>>>(ei);
    k_init<<<NB_NODE, 256>>>();
    k_count<<<NB_EDGE, 256>>>(ei);
    k_dinv<<<NB_NODE, 256>>>();
    k_scan<<<1, 1024>>>();
    k_fill<<<NB_EDGE, 256>>>(ei);

    // conv1: h1 = relu(Â(x@W1) + b1)
    k_tf32gemm<false, false><<<GRID_128, 256>>>(N_NODES, 128, 128, x, -1, W1, nullptr, 0);
    k_aggregate<true, true><<<NB_AGG, 256>>>(0, 1, b1);

    // conv2: h2 = relu(Â(h1@W2) + b2)
    k_tf32gemm<false, false><<<GRID_128, 256>>>(N_NODES, 128, 128, nullptr, 1, W2, nullptr, 0);
    k_aggregate<true, true><<<NB_AGG, 256>>>(0, 1, b2);

    // conv3: h3 = relu((Âh2)@W3 + b3)  -- aggregate at 128-dim, THEN expand to 512
    k_aggregate<false, false><<<NB_AGG, 256>>>(1, 0, nullptr);
    k_tf32gemm<true, true><<<GRID_512, 256>>>(N_NODES, 512, 128, nullptr, 0, W3, b3, 2);

    // MLP: h4 = relu(h3@Wi + bi); out = h4@Wc + bc
    k_tf32gemm<true, true><<<GRID_512, 256>>>(N_NODES, 512, 512, nullptr, 2, Wi, bi, 3);
    k_final<<<NB_AGG, 256>>>(Wc, bc, out);
}

// round 12
// speedup vs baseline: 1.8649x; 1.0280x over previous
#include <cuda_runtime.h>
#include <cstdint>

#define N_NODES 100000
#define N_EDGES 3200000

// ---------------- device scratch (static globals; allocation-free) ----------
__device__ int   g_is64;
__device__ int   g_deg[N_NODES];
__device__ int   g_fill[N_NODES];
__device__ float g_dinv[N_NODES];
__device__ int   g_rowptr[N_NODES + 1];
__device__ int   g_col[N_EDGES];
__device__ __align__(16) float g_wgt[N_EDGES];
__device__ __align__(16) float g_bufA[(size_t)N_NODES * 128];
__device__ __align__(16) float g_bufB[(size_t)N_NODES * 128];
__device__ __align__(16) float g_h3[(size_t)N_NODES * 512];
__device__ __align__(16) float g_h4[(size_t)N_NODES * 512];

__device__ __forceinline__ float* get_buf(int id) {
    switch (id) {
        case 0: return g_bufA;
        case 1: return g_bufB;
        case 2: return g_h3;
        default: return g_h4;
    }
}

__device__ __forceinline__ int edge_at(const void* __restrict__ ei, size_t i) {
    if (g_is64) return (int)((const long long*)ei)[i];
    return ((const int*)ei)[i];
}

// Parallel dtype detect: 256 threads each probe one int64-view entry; data is
// int64 iff all probes are valid node ids. (int32 pairs viewed as int64 are
// >= 2^32 with prob ~1-1e-5 per entry.)
__global__ void k_detect(const void* __restrict__ ei) {
    __shared__ int s_bad;
    if (threadIdx.x == 0) s_bad = 0;
    __syncthreads();
    const long long* p = (const long long*)ei;
    long long v = p[threadIdx.x];
    if (v < 0 || v >= N_NODES) atomicOr(&s_bad, 1);
    __syncthreads();
    if (threadIdx.x == 0) g_is64 = !s_bad;
}

// ---------------- graph preprocessing ---------------------------------------
__global__ void k_init() {
    int i = blockIdx.x * blockDim.x + threadIdx.x;
    if (i < N_NODES) { g_deg[i] = 1; g_fill[i] = 0; }   // deg starts at 1 (self loop)
}

__global__ void k_count(const void* __restrict__ ei) {
    int e = blockIdx.x * blockDim.x + threadIdx.x;
    if (e < N_EDGES) {
        int d = edge_at(ei, (size_t)N_EDGES + e);
        atomicAdd(&g_deg[d], 1);
    }
}

__global__ void k_dinv() {
    int i = blockIdx.x * blockDim.x + threadIdx.x;
    if (i < N_NODES) g_dinv[i] = rsqrtf((float)g_deg[i]);
}

// single-block exclusive scan of (deg-1) -> rowptr
__global__ void k_scan() {
    __shared__ int warp_sums[32];
    __shared__ int s_carry;
    const int BS = 1024;
    int tid = threadIdx.x, lane = tid & 31, wid = tid >> 5;
    if (tid == 0) { s_carry = 0; g_rowptr[0] = 0; }
    __syncthreads();
    for (int base = 0; base < N_NODES; base += BS) {
        int i = base + tid;
        int v = (i < N_NODES) ? (g_deg[i] - 1) : 0;
        int x = v;
        #pragma unroll
        for (int o = 1; o < 32; o <<= 1) {
            int n = __shfl_up_sync(0xffffffffu, x, o);
            if (lane >= o) x += n;
        }
        if (lane == 31) warp_sums[wid] = x;
        __syncthreads();
        if (wid == 0) {
            int s = warp_sums[lane];
            #pragma unroll
            for (int o = 1; o < 32; o <<= 1) {
                int n = __shfl_up_sync(0xffffffffu, s, o);
                if (lane >= o) s += n;
            }
            warp_sums[lane] = s;
        }
        __syncthreads();
        int warp_off = (wid > 0) ? warp_sums[wid - 1] : 0;
        int incl = x + warp_off + s_carry;
        if (i < N_NODES) g_rowptr[i + 1] = incl;
        __syncthreads();
        if (tid == BS - 1) s_carry = incl;
        __syncthreads();
    }
}

__global__ void k_fill(const void* __restrict__ ei) {
    int e = blockIdx.x * blockDim.x + threadIdx.x;
    if (e < N_EDGES) {
        int s = edge_at(ei, e);
        int d = edge_at(ei, (size_t)N_EDGES + e);
        int p = g_rowptr[d] + atomicAdd(&g_fill[d], 1);
        g_col[p] = s;
        g_wgt[p] = g_dinv[s] * g_dinv[d];
    }
}

// ---------------- aggregation: one warp per node, 128 features ---------------
template<bool BIAS, bool RELU>
__global__ void k_aggregate(int in_id, int out_id, const float* __restrict__ bias) {
    const float* hin = get_buf(in_id);
    float* hout = get_buf(out_id);
    int lane = threadIdx.x & 31;
    int node = blockIdx.x * (blockDim.x >> 5) + (threadIdx.x >> 5);
    if (node >= N_NODES) return;

    float dv = g_dinv[node];
    float4 acc = ((const float4*)(hin + (size_t)node * 128))[lane];
    float sw = dv * dv;
    acc.x *= sw; acc.y *= sw; acc.z *= sw; acc.w *= sw;

    int e = g_rowptr[node];
    int end = g_rowptr[node + 1];
    for (; e + 2 <= end; e += 2) {
        int s0 = __ldg(&g_col[e]);
        int s1 = __ldg(&g_col[e + 1]);
        float w0 = __ldg(&g_wgt[e]);
        float w1 = __ldg(&g_wgt[e + 1]);
        float4 v0 = ((const float4*)(hin + (size_t)s0 * 128))[lane];
        float4 v1 = ((const float4*)(hin + (size_t)s1 * 128))[lane];
        acc.x += v0.x * w0; acc.y += v0.y * w0; acc.z += v0.z * w0; acc.w += v0.w * w0;
        acc.x += v1.x * w1; acc.y += v1.y * w1; acc.z += v1.z * w1; acc.w += v1.w * w1;
    }
    if (e < end) {
        int s0 = __ldg(&g_col[e]);
        float w0 = __ldg(&g_wgt[e]);
        float4 v0 = ((const float4*)(hin + (size_t)s0 * 128))[lane];
        acc.x += v0.x * w0; acc.y += v0.y * w0; acc.z += v0.z * w0; acc.w += v0.w * w0;
    }
    if (BIAS) {
        float4 b4 = ((const float4*)bias)[lane];
        acc.x += b4.x; acc.y += b4.y; acc.z += b4.z; acc.w += b4.w;
    }
    if (RELU) {
        acc.x = fmaxf(acc.x, 0.f); acc.y = fmaxf(acc.y, 0.f);
        acc.z = fmaxf(acc.z, 0.f); acc.w = fmaxf(acc.w, 0.f);
    }
    ((float4*)(hout + (size_t)node * 128))[lane] = acc;
}

// ---------------- TF32 tensor-core GEMM, software-pipelined ------------------
// C[M,N] = A[M,K] @ B[K,N] (+bias)(+relu), fp32 in/out, tf32 mma, fp32 accum.
// BM=BN=128, BK=32, 256 threads = 8 warps (4x2), warp tile 32x64.
// Next k-tile is prefetched into registers while mma consumes smem.
__device__ __forceinline__ uint32_t f2tf32(float f) {
    uint32_t u;
    asm("cvt.rna.tf32.f32 %0, %1;" : "=r"(u) : "f"(f));
    return u;
}

template<bool BIAS, bool RELU>
__global__ __launch_bounds__(256, 2)
void k_tf32gemm(int M, int N, int K,
                const float* __restrict__ Aext, int Aid,
                const float* __restrict__ B,
                const float* __restrict__ bias, int Cid) {
    constexpr int BM = 128, BN = 128, BK = 32;
    const float* A = (Aid >= 0) ? get_buf(Aid) : Aext;
    float* C = get_buf(Cid);

    __shared__ uint32_t As[BK][BM + 4];   // k-major
    __shared__ uint32_t Bs[BK][BN + 4];   // k-major

    const int tid = threadIdx.x;
    const int w = tid >> 5;
    const int lane = tid & 31;
    const int groupID = lane >> 2;        // 0..7
    const int tig = lane & 3;             // 0..3
    const int warp_m = (w & 3) * 32;      // 0,32,64,96
    const int warp_n = (w >> 2) * 64;     // 0,64

    const int block_m = blockIdx.y * BM;
    const int n0 = blockIdx.x * BN;

    float c[2][8][4];
    #pragma unroll
    for (int i = 0; i < 2; i++)
        #pragma unroll
        for (int j = 0; j < 8; j++)
            #pragma unroll
            for (int r = 0; r < 4; r++) c[i][j][r] = 0.f;

    // global-load assignments
    const int arow = tid >> 3;            // 0..31 (+32*it)
    const int akq  = (tid & 7) * 4;       // 0,4,...,28
    const int bkr  = tid >> 5;            // 0..7 (+8*it)
    const int bc4  = (tid & 31) * 4;      // 0..124

    float4 sa[4], sb[4];                  // register staging (prefetch)

    // prologue: load tile 0 into regs
    #pragma unroll
    for (int it = 0; it < 4; it++) {
        int gr = block_m + arow + it * 32;
        sa[it] = (gr < M) ? *(const float4*)(A + (size_t)gr * K + akq)
                          : make_float4(0.f, 0.f, 0.f, 0.f);
        sb[it] = *(const float4*)(B + (size_t)(bkr + it * 8) * N + n0 + bc4);
    }

    for (int k0 = 0; k0 < K; k0 += BK) {
        // commit staged regs to smem (cvt here)
        #pragma unroll
        for (int it = 0; it < 4; it++) {
            int r = arow + it * 32;
            As[akq + 0][r] = f2tf32(sa[it].x);
            As[akq + 1][r] = f2tf32(sa[it].y);
            As[akq + 2][r] = f2tf32(sa[it].z);
            As[akq + 3][r] = f2tf32(sa[it].w);
            int kr = bkr + it * 8;
            Bs[kr][bc4 + 0] = f2tf32(sb[it].x);
            Bs[kr][bc4 + 1] = f2tf32(sb[it].y);
            Bs[kr][bc4 + 2] = f2tf32(sb[it].z);
            Bs[kr][bc4 + 3] = f2tf32(sb[it].w);
        }
        __syncthreads();

        // prefetch next tile into regs (overlaps with mma below)
        const int kn = k0 + BK;
        if (kn < K) {
            #pragma unroll
            for (int it = 0; it < 4; it++) {
                int gr = block_m + arow + it * 32;
                sa[it] = (gr < M) ? *(const float4*)(A + (size_t)gr * K + kn + akq)
                                  : make_float4(0.f, 0.f, 0.f, 0.f);
                sb[it] = *(const float4*)(B + (size_t)(kn + bkr + it * 8) * N + n0 + bc4);
            }
        }

        #pragma unroll
        for (int ks = 0; ks < BK / 8; ks++) {
            const int kb = ks * 8;
            uint32_t af[2][4];
            #pragma unroll
            for (int mt = 0; mt < 2; mt++) {
                int m0 = warp_m + mt * 16;
                af[mt][0] = As[kb + tig    ][m0 + groupID];
                af[mt][1] = As[kb + tig    ][m0 + groupID + 8];
                af[mt][2] = As[kb + tig + 4][m0 + groupID];
                af[mt][3] = As[kb + tig + 4][m0 + groupID + 8];
            }
            uint32_t bf[8][2];
            #pragma unroll
            for (int nt = 0; nt < 8; nt++) {
                int nb = warp_n + nt * 8;
                bf[nt][0] = Bs[kb + tig    ][nb + groupID];
                bf[nt][1] = Bs[kb + tig + 4][nb + groupID];
            }
            #pragma unroll
            for (int mt = 0; mt < 2; mt++)
                #pragma unroll
                for (int nt = 0; nt < 8; nt++) {
                    asm volatile(
                        "mma.sync.aligned.m16n8k8.row.col.f32.tf32.tf32.f32 "
                        "{%0,%1,%2,%3}, {%4,%5,%6,%7}, {%8,%9}, {%0,%1,%2,%3};\n"
                        : "+f"(c[mt][nt][0]), "+f"(c[mt][nt][1]),
                          "+f"(c[mt][nt][2]), "+f"(c[mt][nt][3])
                        : "r"(af[mt][0]), "r"(af[mt][1]), "r"(af[mt][2]), "r"(af[mt][3]),
                          "r"(bf[nt][0]), "r"(bf[nt][1]));
                }
        }
        __syncthreads();
    }

    // epilogue: bias + relu + guarded float2 stores
    #pragma unroll
    for (int nt = 0; nt < 8; nt++) {
        int col = n0 + warp_n + nt * 8 + 2 * tig;
        float b0 = 0.f, b1 = 0.f;
        if (BIAS) { b0 = bias[col]; b1 = bias[col + 1]; }
        #pragma unroll
        for (int mt = 0; mt < 2; mt++) {
            int rbase = block_m + warp_m + mt * 16 + groupID;
            float v0 = c[mt][nt][0] + b0;
            float v1 = c[mt][nt][1] + b1;
            float v2 = c[mt][nt][2] + b0;
            float v3 = c[mt][nt][3] + b1;
            if (RELU) {
                v0 = fmaxf(v0, 0.f); v1 = fmaxf(v1, 0.f);
                v2 = fmaxf(v2, 0.f); v3 = fmaxf(v3, 0.f);
            }
            if (rbase < M)
                *(float2*)(C + (size_t)rbase * N + col) = make_float2(v0, v1);
            if (rbase + 8 < M)
                *(float2*)(C + (size_t)(rbase + 8) * N + col) = make_float2(v2, v3);
        }
    }
}

// ---------------- classification head: out = h4 @ Wc + bc (N=3) --------------
__global__ void k_final(const float* __restrict__ Wc,
                        const float* __restrict__ bc, float* __restrict__ out) {
    const float* h4 = g_h4;
    __shared__ float sW[512 * 3];
    int tid = threadIdx.x;
    for (int i = tid; i < 512 * 3; i += blockDim.x) sW[i] = Wc[i];
    __syncthreads();
    int lane = tid & 31, wid = tid >> 5;
    int node = blockIdx.x * (blockDim.x >> 5) + wid;
    if (node >= N_NODES) return;
    const float* row = h4 + (size_t)node * 512;
    float a0 = 0.f, a1 = 0.f, a2 = 0.f;
    #pragma unroll
    for (int kk = 0; kk < 16; kk++) {
        int k = kk * 32 + lane;
        float v = row[k];
        a0 += v * sW[k * 3 + 0];
        a1 += v * sW[k * 3 + 1];
        a2 += v * sW[k * 3 + 2];
    }
    #pragma unroll
    for (int o = 16; o > 0; o >>= 1) {
        a0 += __shfl_down_sync(0xffffffffu, a0, o);
        a1 += __shfl_down_sync(0xffffffffu, a1, o);
        a2 += __shfl_down_sync(0xffffffffu, a2, o);
    }
    if (lane == 0) {
        out[(size_t)node * 3 + 0] = a0 + bc[0];
        out[(size_t)node * 3 + 1] = a1 + bc[1];
        out[(size_t)node * 3 + 2] = a2 + bc[2];
    }
}

// ---------------- launch -----------------------------------------------------
extern "C" void kernel_launch(void* const* d_in, const int* in_sizes, int n_in,
                              void* d_out, int out_size) {
    const float* x  = (const float*)d_in[0];
    const void*  ei = d_in[1];                 // int32 or int64, auto-detected
    const float* W1 = (const float*)d_in[2];
    const float* b1 = (const float*)d_in[3];
    const float* W2 = (const float*)d_in[4];
    const float* b2 = (const float*)d_in[5];
    const float* W3 = (const float*)d_in[6];
    const float* b3 = (const float*)d_in[7];
    const float* Wi = (const float*)d_in[8];
    const float* bi = (const float*)d_in[9];
    const float* Wc = (const float*)d_in[10];
    const float* bc = (const float*)d_in[11];
    float* out = (float*)d_out;

    // buffer ids: 0 = g_bufA, 1 = g_bufB, 2 = g_h3, 3 = g_h4
    const int NB_NODE = (N_NODES + 255) / 256;        // 391
    const int NB_EDGE = (N_EDGES + 255) / 256;        // 12500
    const int NB_AGG  = (N_NODES + 7) / 8;            // 12500 (8 warps/block)
    const dim3 GRID_128(1, (N_NODES + 127) / 128);    // 782 rows
    const dim3 GRID_512(4, (N_NODES + 127) / 128);

    // graph structure (identical for all convs)
    k_detect<<<1, 256>>>(ei);
    k_init<<<NB_NODE, 256>>>();
    k_count<<<NB_EDGE, 256>>>(ei);
    k_dinv<<<NB_NODE, 256>>>();
    k_scan<<<1, 1024>>>();
    k_fill<<<NB_EDGE, 256>>>(ei);

    // conv1: h1 = relu(Â(x@W1) + b1)
    k_tf32gemm<false, false><<<GRID_128, 256>>>(N_NODES, 128, 128, x, -1, W1, nullptr, 0);
    k_aggregate<true, true><<<NB_AGG, 256>>>(0, 1, b1);

    // conv2: h2 = relu(Â(h1@W2) + b2)
    k_tf32gemm<false, false><<<GRID_128, 256>>>(N_NODES, 128, 128, nullptr, 1, W2, nullptr, 0);
    k_aggregate<true, true><<<NB_AGG, 256>>>(0, 1, b2);

    // conv3: h3 = relu((Âh2)@W3 + b3)  -- aggregate at 128-dim, THEN expand to 512
    k_aggregate<false, false><<<NB_AGG, 256>>>(1, 0, nullptr);
    k_tf32gemm<true, true><<<GRID_512, 256>>>(N_NODES, 512, 128, nullptr, 0, W3, b3, 2);

    // MLP: h4 = relu(h3@Wi + bi); out = h4@Wc + bc
    k_tf32gemm<true, true><<<GRID_512, 256>>>(N_NODES, 512, 512, nullptr, 2, Wi, bi, 3);
    k_final<<<NB_AGG, 256>>>(Wc, bc, out);
}

// round 13
// speedup vs baseline: 2.0382x; 1.0929x over previous
#include <cuda_runtime.h>
#include <cuda_fp16.h>
#include <cstdint>

#define N_NODES 100000
#define N_EDGES 3200000

// ---------------- device scratch (static globals; allocation-free) ----------
__device__ int   g_is64;
__device__ int   g_deg[N_NODES];
__device__ int   g_fill[N_NODES];
__device__ float g_dinv[N_NODES];
__device__ int   g_rowptr[N_NODES + 1];
__device__ int   g_col[N_EDGES];
__device__ __align__(16) float g_wgt[N_EDGES];
__device__ __align__(16) float g_bufA[(size_t)N_NODES * 128];   // also used as half
__device__ __align__(16) float g_bufB[(size_t)N_NODES * 128];
__device__ __align__(16) float g_h3[(size_t)N_NODES * 512];
__device__ __align__(16) float g_h4[(size_t)N_NODES * 512];

__device__ __forceinline__ float* get_buf(int id) {
    switch (id) {
        case 0: return g_bufA;
        case 1: return g_bufB;
        case 2: return g_h3;
        default: return g_h4;
    }
}

__device__ __forceinline__ int edge_at(const void* __restrict__ ei, size_t i) {
    if (g_is64) return (int)((const long long*)ei)[i];
    return ((const int*)ei)[i];
}

// Parallel dtype detect (int32 vs int64 edge_index).
__global__ void k_detect(const void* __restrict__ ei) {
    __shared__ int s_bad;
    if (threadIdx.x == 0) s_bad = 0;
    __syncthreads();
    const long long* p = (const long long*)ei;
    long long v = p[threadIdx.x];
    if (v < 0 || v >= N_NODES) atomicOr(&s_bad, 1);
    __syncthreads();
    if (threadIdx.x == 0) g_is64 = !s_bad;
}

// ---------------- graph preprocessing ---------------------------------------
__global__ void k_init() {
    int i = blockIdx.x * blockDim.x + threadIdx.x;
    if (i < N_NODES) { g_deg[i] = 1; g_fill[i] = 0; }
}

__global__ void k_count(const void* __restrict__ ei) {
    int e = blockIdx.x * blockDim.x + threadIdx.x;
    if (e < N_EDGES) {
        int d = edge_at(ei, (size_t)N_EDGES + e);
        atomicAdd(&g_deg[d], 1);
    }
}

__global__ void k_dinv() {
    int i = blockIdx.x * blockDim.x + threadIdx.x;
    if (i < N_NODES) g_dinv[i] = rsqrtf((float)g_deg[i]);
}

__global__ void k_scan() {
    __shared__ int warp_sums[32];
    __shared__ int s_carry;
    const int BS = 1024;
    int tid = threadIdx.x, lane = tid & 31, wid = tid >> 5;
    if (tid == 0) { s_carry = 0; g_rowptr[0] = 0; }
    __syncthreads();
    for (int base = 0; base < N_NODES; base += BS) {
        int i = base + tid;
        int v = (i < N_NODES) ? (g_deg[i] - 1) : 0;
        int x = v;
        #pragma unroll
        for (int o = 1; o < 32; o <<= 1) {
            int n = __shfl_up_sync(0xffffffffu, x, o);
            if (lane >= o) x += n;
        }
        if (lane == 31) warp_sums[wid] = x;
        __syncthreads();
        if (wid == 0) {
            int s = warp_sums[lane];
            #pragma unroll
            for (int o = 1; o < 32; o <<= 1) {
                int n = __shfl_up_sync(0xffffffffu, s, o);
                if (lane >= o) s += n;
            }
            warp_sums[lane] = s;
        }
        __syncthreads();
        int warp_off = (wid > 0) ? warp_sums[wid - 1] : 0;
        int incl = x + warp_off + s_carry;
        if (i < N_NODES) g_rowptr[i + 1] = incl;
        __syncthreads();
        if (tid == BS - 1) s_carry = incl;
        __syncthreads();
    }
}

__global__ void k_fill(const void* __restrict__ ei) {
    int e = blockIdx.x * blockDim.x + threadIdx.x;
    if (e < N_EDGES) {
        int s = edge_at(ei, e);
        int d = edge_at(ei, (size_t)N_EDGES + e);
        int p = g_rowptr[d] + atomicAdd(&g_fill[d], 1);
        g_col[p] = s;
        g_wgt[p] = g_dinv[s] * g_dinv[d];
    }
}

// ---------------- half helpers ----------------------------------------------
__device__ __forceinline__ float4 h4_to_f4(uint2 u) {
    __half2 a = *(__half2*)&u.x;
    __half2 b = *(__half2*)&u.y;
    float2 fa = __half22float2(a), fb = __half22float2(b);
    return make_float4(fa.x, fa.y, fb.x, fb.y);
}
__device__ __forceinline__ uint2 f4_to_h4(float4 v) {
    __half2 a = __floats2half2_rn(v.x, v.y);
    __half2 b = __floats2half2_rn(v.z, v.w);
    uint2 u;
    u.x = *(uint32_t*)&a;
    u.y = *(uint32_t*)&b;
    return u;
}

// ------- aggregation: one warp per node, 128 features, fp16 in, fp16 out -----
template<bool BIAS, bool RELU>
__global__ void k_aggregate(int in_id, int out_id, const float* __restrict__ bias) {
    const __half* hin = (const __half*)get_buf(in_id);
    __half* hout = (__half*)get_buf(out_id);
    int lane = threadIdx.x & 31;
    int node = blockIdx.x * (blockDim.x >> 5) + (threadIdx.x >> 5);
    if (node >= N_NODES) return;

    float dv = g_dinv[node];
    float sw = dv * dv;
    float4 acc = h4_to_f4(((const uint2*)(hin + (size_t)node * 128))[lane]);
    acc.x *= sw; acc.y *= sw; acc.z *= sw; acc.w *= sw;

    int e = g_rowptr[node];
    int end = g_rowptr[node + 1];
    for (; e + 2 <= end; e += 2) {
        int s0 = __ldg(&g_col[e]);
        int s1 = __ldg(&g_col[e + 1]);
        float w0 = __ldg(&g_wgt[e]);
        float w1 = __ldg(&g_wgt[e + 1]);
        float4 v0 = h4_to_f4(((const uint2*)(hin + (size_t)s0 * 128))[lane]);
        float4 v1 = h4_to_f4(((const uint2*)(hin + (size_t)s1 * 128))[lane]);
        acc.x += v0.x * w0; acc.y += v0.y * w0; acc.z += v0.z * w0; acc.w += v0.w * w0;
        acc.x += v1.x * w1; acc.y += v1.y * w1; acc.z += v1.z * w1; acc.w += v1.w * w1;
    }
    if (e < end) {
        int s0 = __ldg(&g_col[e]);
        float w0 = __ldg(&g_wgt[e]);
        float4 v0 = h4_to_f4(((const uint2*)(hin + (size_t)s0 * 128))[lane]);
        acc.x += v0.x * w0; acc.y += v0.y * w0; acc.z += v0.z * w0; acc.w += v0.w * w0;
    }
    if (BIAS) {
        float4 b4 = ((const float4*)bias)[lane];
        acc.x += b4.x; acc.y += b4.y; acc.z += b4.z; acc.w += b4.w;
    }
    if (RELU) {
        acc.x = fmaxf(acc.x, 0.f); acc.y = fmaxf(acc.y, 0.f);
        acc.z = fmaxf(acc.z, 0.f); acc.w = fmaxf(acc.w, 0.f);
    }
    ((uint2*)(hout + (size_t)node * 128))[lane] = f4_to_h4(acc);
}

// ---------------- TF32 tensor-core GEMM, software-pipelined ------------------
// A: fp32 or fp16 (template), B/bias: fp32, C: fp16. fp32 accumulate.
__device__ __forceinline__ uint32_t f2tf32(float f) {
    uint32_t u;
    asm("cvt.rna.tf32.f32 %0, %1;" : "=r"(u) : "f"(f));
    return u;
}

template<class T> __device__ __forceinline__ float4 load4(const T* p);
template<> __device__ __forceinline__ float4 load4<float>(const float* p) {
    return *(const float4*)p;
}
template<> __device__ __forceinline__ float4 load4<__half>(const __half* p) {
    return h4_to_f4(*(const uint2*)p);
}

template<class TA, bool BIAS, bool RELU>
__global__ __launch_bounds__(256, 2)
void k_tf32gemm(int M, int N, int K,
                const void* __restrict__ Aext, int Aid,
                const float* __restrict__ B,
                const float* __restrict__ bias, int Cid) {
    constexpr int BM = 128, BN = 128, BK = 32;
    const TA* A = (Aid >= 0) ? (const TA*)get_buf(Aid) : (const TA*)Aext;
    __half* C = (__half*)get_buf(Cid);

    __shared__ uint32_t As[BK][BM + 4];   // k-major tf32
    __shared__ uint32_t Bs[BK][BN + 4];

    const int tid = threadIdx.x;
    const int w = tid >> 5;
    const int lane = tid & 31;
    const int groupID = lane >> 2;
    const int tig = lane & 3;
    const int warp_m = (w & 3) * 32;
    const int warp_n = (w >> 2) * 64;

    const int block_m = blockIdx.y * BM;
    const int n0 = blockIdx.x * BN;

    float c[2][8][4];
    #pragma unroll
    for (int i = 0; i < 2; i++)
        #pragma unroll
        for (int j = 0; j < 8; j++)
            #pragma unroll
            for (int r = 0; r < 4; r++) c[i][j][r] = 0.f;

    const int arow = tid >> 3;
    const int akq  = (tid & 7) * 4;
    const int bkr  = tid >> 5;
    const int bc4  = (tid & 31) * 4;

    float4 sa[4], sb[4];

    #pragma unroll
    for (int it = 0; it < 4; it++) {
        int gr = block_m + arow + it * 32;
        sa[it] = (gr < M) ? load4<TA>(A + (size_t)gr * K + akq)
                          : make_float4(0.f, 0.f, 0.f, 0.f);
        sb[it] = *(const float4*)(B + (size_t)(bkr + it * 8) * N + n0 + bc4);
    }

    for (int k0 = 0; k0 < K; k0 += BK) {
        #pragma unroll
        for (int it = 0; it < 4; it++) {
            int r = arow + it * 32;
            As[akq + 0][r] = f2tf32(sa[it].x);
            As[akq + 1][r] = f2tf32(sa[it].y);
            As[akq + 2][r] = f2tf32(sa[it].z);
            As[akq + 3][r] = f2tf32(sa[it].w);
            int kr = bkr + it * 8;
            Bs[kr][bc4 + 0] = f2tf32(sb[it].x);
            Bs[kr][bc4 + 1] = f2tf32(sb[it].y);
            Bs[kr][bc4 + 2] = f2tf32(sb[it].z);
            Bs[kr][bc4 + 3] = f2tf32(sb[it].w);
        }
        __syncthreads();

        const int kn = k0 + BK;
        if (kn < K) {
            #pragma unroll
            for (int it = 0; it < 4; it++) {
                int gr = block_m + arow + it * 32;
                sa[it] = (gr < M) ? load4<TA>(A + (size_t)gr * K + kn + akq)
                                  : make_float4(0.f, 0.f, 0.f, 0.f);
                sb[it] = *(const float4*)(B + (size_t)(kn + bkr + it * 8) * N + n0 + bc4);
            }
        }

        #pragma unroll
        for (int ks = 0; ks < BK / 8; ks++) {
            const int kb = ks * 8;
            uint32_t af[2][4];
            #pragma unroll
            for (int mt = 0; mt < 2; mt++) {
                int m0 = warp_m + mt * 16;
                af[mt][0] = As[kb + tig    ][m0 + groupID];
                af[mt][1] = As[kb + tig    ][m0 + groupID + 8];
                af[mt][2] = As[kb + tig + 4][m0 + groupID];
                af[mt][3] = As[kb + tig + 4][m0 + groupID + 8];
            }
            uint32_t bf[8][2];
            #pragma unroll
            for (int nt = 0; nt < 8; nt++) {
                int nb = warp_n + nt * 8;
                bf[nt][0] = Bs[kb + tig    ][nb + groupID];
                bf[nt][1] = Bs[kb + tig + 4][nb + groupID];
            }
            #pragma unroll
            for (int mt = 0; mt < 2; mt++)
                #pragma unroll
                for (int nt = 0; nt < 8; nt++) {
                    asm volatile(
                        "mma.sync.aligned.m16n8k8.row.col.f32.tf32.tf32.f32 "
                        "{%0,%1,%2,%3}, {%4,%5,%6,%7}, {%8,%9}, {%0,%1,%2,%3};\n"
                        : "+f"(c[mt][nt][0]), "+f"(c[mt][nt][1]),
                          "+f"(c[mt][nt][2]), "+f"(c[mt][nt][3])
                        : "r"(af[mt][0]), "r"(af[mt][1]), "r"(af[mt][2]), "r"(af[mt][3]),
                          "r"(bf[nt][0]), "r"(bf[nt][1]));
                }
        }
        __syncthreads();
    }

    // epilogue: bias + relu + fp16 stores (half2)
    #pragma unroll
    for (int nt = 0; nt < 8; nt++) {
        int col = n0 + warp_n + nt * 8 + 2 * tig;
        float b0 = 0.f, b1 = 0.f;
        if (BIAS) { b0 = bias[col]; b1 = bias[col + 1]; }
        #pragma unroll
        for (int mt = 0; mt < 2; mt++) {
            int rbase = block_m + warp_m + mt * 16 + groupID;
            float v0 = c[mt][nt][0] + b0;
            float v1 = c[mt][nt][1] + b1;
            float v2 = c[mt][nt][2] + b0;
            float v3 = c[mt][nt][3] + b1;
            if (RELU) {
                v0 = fmaxf(v0, 0.f); v1 = fmaxf(v1, 0.f);
                v2 = fmaxf(v2, 0.f); v3 = fmaxf(v3, 0.f);
            }
            if (rbase < M)
                *(__half2*)(C + (size_t)rbase * N + col) = __floats2half2_rn(v0, v1);
            if (rbase + 8 < M)
                *(__half2*)(C + (size_t)(rbase + 8) * N + col) = __floats2half2_rn(v2, v3);
        }
    }
}

// ---------------- classification head: out = h4 @ Wc + bc (N=3) --------------
__global__ void k_final(const float* __restrict__ Wc,
                        const float* __restrict__ bc, float* __restrict__ out) {
    const __half* h4 = (const __half*)g_h4;
    __shared__ float sW[512 * 3];
    int tid = threadIdx.x;
    for (int i = tid; i < 512 * 3; i += blockDim.x) sW[i] = Wc[i];
    __syncthreads();
    int lane = tid & 31, wid = tid >> 5;
    int node = blockIdx.x * (blockDim.x >> 5) + wid;
    if (node >= N_NODES) return;
    const __half* row = h4 + (size_t)node * 512;
    float a0 = 0.f, a1 = 0.f, a2 = 0.f;
    #pragma unroll
    for (int kk = 0; kk < 8; kk++) {
        int k = kk * 64 + lane * 2;
        __half2 hv = *(const __half2*)(row + k);
        float2 fv = __half22float2(hv);
        a0 += fv.x * sW[k * 3 + 0] + fv.y * sW[(k + 1) * 3 + 0];
        a1 += fv.x * sW[k * 3 + 1] + fv.y * sW[(k + 1) * 3 + 1];
        a2 += fv.x * sW[k * 3 + 2] + fv.y * sW[(k + 1) * 3 + 2];
    }
    #pragma unroll
    for (int o = 16; o > 0; o >>= 1) {
        a0 += __shfl_down_sync(0xffffffffu, a0, o);
        a1 += __shfl_down_sync(0xffffffffu, a1, o);
        a2 += __shfl_down_sync(0xffffffffu, a2, o);
    }
    if (lane == 0) {
        out[(size_t)node * 3 + 0] = a0 + bc[0];
        out[(size_t)node * 3 + 1] = a1 + bc[1];
        out[(size_t)node * 3 + 2] = a2 + bc[2];
    }
}

// ---------------- launch -----------------------------------------------------
extern "C" void kernel_launch(void* const* d_in, const int* in_sizes, int n_in,
                              void* d_out, int out_size) {
    const float* x  = (const float*)d_in[0];
    const void*  ei = d_in[1];
    const float* W1 = (const float*)d_in[2];
    const float* b1 = (const float*)d_in[3];
    const float* W2 = (const float*)d_in[4];
    const float* b2 = (const float*)d_in[5];
    const float* W3 = (const float*)d_in[6];
    const float* b3 = (const float*)d_in[7];
    const float* Wi = (const float*)d_in[8];
    const float* bi = (const float*)d_in[9];
    const float* Wc = (const float*)d_in[10];
    const float* bc = (const float*)d_in[11];
    float* out = (float*)d_out;

    // buffer ids: 0 = g_bufA, 1 = g_bufB, 2 = g_h3, 3 = g_h4 (all used as half)
    const int NB_NODE = (N_NODES + 255) / 256;
    const int NB_EDGE = (N_EDGES + 255) / 256;
    const int NB_AGG  = (N_NODES + 7) / 8;
    const dim3 GRID_128(1, (N_NODES + 127) / 128);
    const dim3 GRID_512(4, (N_NODES + 127) / 128);

    // graph structure
    k_detect<<<1, 256>>>(ei);
    k_init<<<NB_NODE, 256>>>();
    k_count<<<NB_EDGE, 256>>>(ei);
    k_dinv<<<NB_NODE, 256>>>();
    k_scan<<<1, 1024>>>();
    k_fill<<<NB_EDGE, 256>>>(ei);

    // conv1: h1 = relu(Â(x@W1) + b1)        [x fp32 -> half chain]
    k_tf32gemm<float, false, false><<<GRID_128, 256>>>(N_NODES, 128, 128, x, -1, W1, nullptr, 0);
    k_aggregate<true, true><<<NB_AGG, 256>>>(0, 1, b1);

    // conv2: h2 = relu(Â(h1@W2) + b2)
    k_tf32gemm<__half, false, false><<<GRID_128, 256>>>(N_NODES, 128, 128, nullptr, 1, W2, nullptr, 0);
    k_aggregate<true, true><<<NB_AGG, 256>>>(0, 1, b2);

    // conv3: h3 = relu((Âh2)@W3 + b3) -- aggregate at 128-dim, then expand
    k_aggregate<false, false><<<NB_AGG, 256>>>(1, 0, nullptr);
    k_tf32gemm<__half, true, true><<<GRID_512, 256>>>(N_NODES, 512, 128, nullptr, 0, W3, b3, 2);

    // MLP: h4 = relu(h3@Wi + bi); out = h4@Wc + bc
    k_tf32gemm<__half, true, true><<<GRID_512, 256>>>(N_NODES, 512, 512, nullptr, 2, Wi, bi, 3);
    k_final<<<NB_AGG, 256>>>(Wc, bc, out);
}

// round 14
// speedup vs baseline: 2.7075x; 1.3284x over previous
#include <cuda_runtime.h>
#include <cuda_fp16.h>
#include <cstdint>

#define N_NODES 100000
#define N_EDGES 3200000

// ---------------- device scratch (static globals; allocation-free) ----------
__device__ int   g_is64;
__device__ int   g_deg[N_NODES];
__device__ int   g_fill[N_NODES];
__device__ float g_dinv[N_NODES];
__device__ int   g_rowptr[N_NODES + 1];
__device__ int   g_col[N_EDGES];
__device__ __align__(16) float g_wgt[N_EDGES];
__device__ __align__(16) float g_bufA[(size_t)N_NODES * 128];   // used as half
__device__ __align__(16) float g_bufB[(size_t)N_NODES * 128];
__device__ __align__(16) float g_h3[(size_t)N_NODES * 512];
__device__ __align__(16) float g_h4[(size_t)N_NODES * 512];
// fp16 transposed weights: W1t[128*128], W2t[128*128], W3t[512*128], Wit[512*512]
#define WOFF_W1 0
#define WOFF_W2 16384
#define WOFF_W3 32768
#define WOFF_WI 98304
__device__ __align__(16) __half g_wT[98304 + 262144];

__device__ __forceinline__ float* get_buf(int id) {
    switch (id) {
        case 0: return g_bufA;
        case 1: return g_bufB;
        case 2: return g_h3;
        default: return g_h4;
    }
}

__device__ __forceinline__ int edge_at(const void* __restrict__ ei, size_t i) {
    if (g_is64) return (int)((const long long*)ei)[i];
    return ((const int*)ei)[i];
}

__global__ void k_detect(const void* __restrict__ ei) {
    __shared__ int s_bad;
    if (threadIdx.x == 0) s_bad = 0;
    __syncthreads();
    const long long* p = (const long long*)ei;
    long long v = p[threadIdx.x];
    if (v < 0 || v >= N_NODES) atomicOr(&s_bad, 1);
    __syncthreads();
    if (threadIdx.x == 0) g_is64 = !s_bad;
}

// ---------------- graph preprocessing ---------------------------------------
__global__ void k_init() {
    int i = blockIdx.x * blockDim.x + threadIdx.x;
    if (i < N_NODES) { g_deg[i] = 1; g_fill[i] = 0; }
}

__global__ void k_count(const void* __restrict__ ei) {
    int e = blockIdx.x * blockDim.x + threadIdx.x;
    if (e < N_EDGES) {
        int d = edge_at(ei, (size_t)N_EDGES + e);
        atomicAdd(&g_deg[d], 1);
    }
}

__global__ void k_dinv() {
    int i = blockIdx.x * blockDim.x + threadIdx.x;
    if (i < N_NODES) g_dinv[i] = rsqrtf((float)g_deg[i]);
}

__global__ void k_scan() {
    __shared__ int warp_sums[32];
    __shared__ int s_carry;
    const int BS = 1024;
    int tid = threadIdx.x, lane = tid & 31, wid = tid >> 5;
    if (tid == 0) { s_carry = 0; g_rowptr[0] = 0; }
    __syncthreads();
    for (int base = 0; base < N_NODES; base += BS) {
        int i = base + tid;
        int v = (i < N_NODES) ? (g_deg[i] - 1) : 0;
        int x = v;
        #pragma unroll
        for (int o = 1; o < 32; o <<= 1) {
            int n = __shfl_up_sync(0xffffffffu, x, o);
            if (lane >= o) x += n;
        }
        if (lane == 31) warp_sums[wid] = x;
        __syncthreads();
        if (wid == 0) {
            int s = warp_sums[lane];
            #pragma unroll
            for (int o = 1; o < 32; o <<= 1) {
                int n = __shfl_up_sync(0xffffffffu, s, o);
                if (lane >= o) s += n;
            }
            warp_sums[lane] = s;
        }
        __syncthreads();
        int warp_off = (wid > 0) ? warp_sums[wid - 1] : 0;
        int incl = x + warp_off + s_carry;
        if (i < N_NODES) g_rowptr[i + 1] = incl;
        __syncthreads();
        if (tid == BS - 1) s_carry = incl;
        __syncthreads();
    }
}

__global__ void k_fill(const void* __restrict__ ei) {
    int e = blockIdx.x * blockDim.x + threadIdx.x;
    if (e < N_EDGES) {
        int s = edge_at(ei, e);
        int d = edge_at(ei, (size_t)N_EDGES + e);
        int p = g_rowptr[d] + atomicAdd(&g_fill[d], 1);
        g_col[p] = s;
        g_wgt[p] = g_dinv[s] * g_dinv[d];
    }
}

// ---------------- one-time conversions ---------------------------------------
// transpose+convert weight W[K][N] fp32 -> g_wT[woff + n*K + k] fp16
__global__ void k_wt(const float* __restrict__ W, int K, int N, int woff) {
    int idx = blockIdx.x * blockDim.x + threadIdx.x;
    if (idx < K * N) {
        int k = idx / N, n = idx % N;
        g_wT[woff + n * K + k] = __float2half(W[idx]);
    }
}

// convert x fp32 -> fp16 into buf3 (g_h4)
__global__ void k_cvt(const float* __restrict__ x) {
    int i = blockIdx.x * blockDim.x + threadIdx.x;
    __half* dst = (__half*)g_h4;
    if (i < N_NODES * 128 / 4) {
        float4 v = ((const float4*)x)[i];
        __half2 a = __floats2half2_rn(v.x, v.y);
        __half2 b = __floats2half2_rn(v.z, v.w);
        uint2 u;
        u.x = *(uint32_t*)&a; u.y = *(uint32_t*)&b;
        ((uint2*)dst)[i] = u;
    }
}

// ---------------- half helpers ----------------------------------------------
__device__ __forceinline__ float4 h4_to_f4(uint2 u) {
    __half2 a = *(__half2*)&u.x;
    __half2 b = *(__half2*)&u.y;
    float2 fa = __half22float2(a), fb = __half22float2(b);
    return make_float4(fa.x, fa.y, fb.x, fb.y);
}
__device__ __forceinline__ uint2 f4_to_h4(float4 v) {
    __half2 a = __floats2half2_rn(v.x, v.y);
    __half2 b = __floats2half2_rn(v.z, v.w);
    uint2 u;
    u.x = *(uint32_t*)&a;
    u.y = *(uint32_t*)&b;
    return u;
}

// ------- aggregation: one warp per node, 128 features, fp16 in/out -----------
template<bool BIAS, bool RELU>
__global__ void k_aggregate(int in_id, int out_id, const float* __restrict__ bias) {
    const __half* hin = (const __half*)get_buf(in_id);
    __half* hout = (__half*)get_buf(out_id);
    int lane = threadIdx.x & 31;
    int node = blockIdx.x * (blockDim.x >> 5) + (threadIdx.x >> 5);
    if (node >= N_NODES) return;

    float dv = g_dinv[node];
    float sw = dv * dv;
    float4 acc = h4_to_f4(((const uint2*)(hin + (size_t)node * 128))[lane]);
    acc.x *= sw; acc.y *= sw; acc.z *= sw; acc.w *= sw;

    int e = g_rowptr[node];
    int end = g_rowptr[node + 1];
    for (; e + 2 <= end; e += 2) {
        int s0 = __ldg(&g_col[e]);
        int s1 = __ldg(&g_col[e + 1]);
        float w0 = __ldg(&g_wgt[e]);
        float w1 = __ldg(&g_wgt[e + 1]);
        float4 v0 = h4_to_f4(((const uint2*)(hin + (size_t)s0 * 128))[lane]);
        float4 v1 = h4_to_f4(((const uint2*)(hin + (size_t)s1 * 128))[lane]);
        acc.x += v0.x * w0; acc.y += v0.y * w0; acc.z += v0.z * w0; acc.w += v0.w * w0;
        acc.x += v1.x * w1; acc.y += v1.y * w1; acc.z += v1.z * w1; acc.w += v1.w * w1;
    }
    if (e < end) {
        int s0 = __ldg(&g_col[e]);
        float w0 = __ldg(&g_wgt[e]);
        float4 v0 = h4_to_f4(((const uint2*)(hin + (size_t)s0 * 128))[lane]);
        acc.x += v0.x * w0; acc.y += v0.y * w0; acc.z += v0.z * w0; acc.w += v0.w * w0;
    }
    if (BIAS) {
        float4 b4 = ((const float4*)bias)[lane];
        acc.x += b4.x; acc.y += b4.y; acc.z += b4.z; acc.w += b4.w;
    }
    if (RELU) {
        acc.x = fmaxf(acc.x, 0.f); acc.y = fmaxf(acc.y, 0.f);
        acc.z = fmaxf(acc.z, 0.f); acc.w = fmaxf(acc.w, 0.f);
    }
    ((uint2*)(hout + (size_t)node * 128))[lane] = f4_to_h4(acc);
}

// ---------------- fp16 tensor-core GEMM, software-pipelined ------------------
// C[M,N] = A[M,K] @ W[K,N] (+bias)(+relu); A fp16 [M][K], Wt fp16 [N][K] in
// g_wT (+woff), C fp16. mma.m16n8k16 f32.f16.f16.f32.
// BM=BN=128, BK=32, 256 threads = 8 warps (4x2), warp tile 32x64.
template<bool BIAS, bool RELU>
__global__ __launch_bounds__(256, 2)
void k_hgemm(int M, int N, int K, int Aid, int woff,
             const float* __restrict__ bias, int Cid) {
    constexpr int BM = 128, BN = 128, BK = 32, LDS = 40;  // 40-half row stride
    const __half* A = (const __half*)get_buf(Aid);
    const __half* Bt = g_wT + woff;
    __half* C = (__half*)get_buf(Cid);

    __shared__ __align__(16) __half As[BM][LDS];   // [m][k]
    __shared__ __align__(16) __half Bs[BN][LDS];   // [n][k]

    const int tid = threadIdx.x;
    const int w = tid >> 5;
    const int lane = tid & 31;
    const int groupID = lane >> 2;
    const int tig = lane & 3;
    const int warp_m = (w & 3) * 32;
    const int warp_n = (w >> 2) * 64;

    const int block_m = blockIdx.y * BM;
    const int n0 = blockIdx.x * BN;

    float c[2][8][4];
    #pragma unroll
    for (int i = 0; i < 2; i++)
        #pragma unroll
        for (int j = 0; j < 8; j++)
            #pragma unroll
            for (int r = 0; r < 4; r++) c[i][j][r] = 0.f;

    // global-load assignment: each thread loads 16 halves of A and of B
    const int lrow = tid >> 1;            // 0..127
    const int lk   = (tid & 1) * 16;      // 0 or 16

    const int ga_row = block_m + lrow;
    const bool a_ok = ga_row < M;
    const __half* gA = A + (size_t)ga_row * K + lk;
    const __half* gB = Bt + (size_t)(n0 + lrow) * K + lk;

    uint4 sa0, sa1, sb0, sb1;
    const uint4 z4 = make_uint4(0, 0, 0, 0);

    // prologue
    sa0 = a_ok ? *(const uint4*)(gA)     : z4;
    sa1 = a_ok ? *(const uint4*)(gA + 8) : z4;
    sb0 = *(const uint4*)(gB);
    sb1 = *(const uint4*)(gB + 8);

    for (int k0 = 0; k0 < K; k0 += BK) {
        *(uint4*)&As[lrow][lk]     = sa0;
        *(uint4*)&As[lrow][lk + 8] = sa1;
        *(uint4*)&Bs[lrow][lk]     = sb0;
        *(uint4*)&Bs[lrow][lk + 8] = sb1;
        __syncthreads();

        const int kn = k0 + BK;
        if (kn < K) {
            sa0 = a_ok ? *(const uint4*)(gA + kn)     : z4;
            sa1 = a_ok ? *(const uint4*)(gA + kn + 8) : z4;
            sb0 = *(const uint4*)(gB + kn);
            sb1 = *(const uint4*)(gB + kn + 8);
        }

        #pragma unroll
        for (int ks = 0; ks < BK / 16; ks++) {
            const int kw = ks * 8;        // b32 column base (k/2)
            uint32_t af[2][4];
            #pragma unroll
            for (int mt = 0; mt < 2; mt++) {
                int m0 = warp_m + mt * 16;
                const uint32_t* r0 = (const uint32_t*)&As[m0 + groupID][0];
                const uint32_t* r1 = (const uint32_t*)&As[m0 + groupID + 8][0];
                af[mt][0] = r0[kw + tig];
                af[mt][1] = r1[kw + tig];
                af[mt][2] = r0[kw + tig + 4];
                af[mt][3] = r1[kw + tig + 4];
            }
            uint32_t bf[8][2];
            #pragma unroll
            for (int nt = 0; nt < 8; nt++) {
                const uint32_t* rn = (const uint32_t*)&Bs[warp_n + nt * 8 + groupID][0];
                bf[nt][0] = rn[kw + tig];
                bf[nt][1] = rn[kw + tig + 4];
            }
            #pragma unroll
            for (int mt = 0; mt < 2; mt++)
                #pragma unroll
                for (int nt = 0; nt < 8; nt++) {
                    asm volatile(
                        "mma.sync.aligned.m16n8k16.row.col.f32.f16.f16.f32 "
                        "{%0,%1,%2,%3}, {%4,%5,%6,%7}, {%8,%9}, {%0,%1,%2,%3};\n"
                        : "+f"(c[mt][nt][0]), "+f"(c[mt][nt][1]),
                          "+f"(c[mt][nt][2]), "+f"(c[mt][nt][3])
                        : "r"(af[mt][0]), "r"(af[mt][1]), "r"(af[mt][2]), "r"(af[mt][3]),
                          "r"(bf[nt][0]), "r"(bf[nt][1]));
                }
        }
        __syncthreads();
    }

    // epilogue: bias + relu + fp16 stores
    #pragma unroll
    for (int nt = 0; nt < 8; nt++) {
        int col = n0 + warp_n + nt * 8 + 2 * tig;
        float b0 = 0.f, b1 = 0.f;
        if (BIAS) { b0 = bias[col]; b1 = bias[col + 1]; }
        #pragma unroll
        for (int mt = 0; mt < 2; mt++) {
            int rbase = block_m + warp_m + mt * 16 + groupID;
            float v0 = c[mt][nt][0] + b0;
            float v1 = c[mt][nt][1] + b1;
            float v2 = c[mt][nt][2] + b0;
            float v3 = c[mt][nt][3] + b1;
            if (RELU) {
                v0 = fmaxf(v0, 0.f); v1 = fmaxf(v1, 0.f);
                v2 = fmaxf(v2, 0.f); v3 = fmaxf(v3, 0.f);
            }
            if (rbase < M)
                *(__half2*)(C + (size_t)rbase * N + col) = __floats2half2_rn(v0, v1);
            if (rbase + 8 < M)
                *(__half2*)(C + (size_t)(rbase + 8) * N + col) = __floats2half2_rn(v2, v3);
        }
    }
}

// ---------------- classification head: out = h4 @ Wc + bc (N=3) --------------
__global__ void k_final(const float* __restrict__ Wc,
                        const float* __restrict__ bc, float* __restrict__ out) {
    const __half* h4 = (const __half*)g_h4;
    __shared__ float sW[512 * 3];
    int tid = threadIdx.x;
    for (int i = tid; i < 512 * 3; i += blockDim.x) sW[i] = Wc[i];
    __syncthreads();
    int lane = tid & 31, wid = tid >> 5;
    int node = blockIdx.x * (blockDim.x >> 5) + wid;
    if (node >= N_NODES) return;
    const __half* row = h4 + (size_t)node * 512;
    float a0 = 0.f, a1 = 0.f, a2 = 0.f;
    #pragma unroll
    for (int kk = 0; kk < 8; kk++) {
        int k = kk * 64 + lane * 2;
        __half2 hv = *(const __half2*)(row + k);
        float2 fv = __half22float2(hv);
        a0 += fv.x * sW[k * 3 + 0] + fv.y * sW[(k + 1) * 3 + 0];
        a1 += fv.x * sW[k * 3 + 1] + fv.y * sW[(k + 1) * 3 + 1];
        a2 += fv.x * sW[k * 3 + 2] + fv.y * sW[(k + 1) * 3 + 2];
    }
    #pragma unroll
    for (int o = 16; o > 0; o >>= 1) {
        a0 += __shfl_down_sync(0xffffffffu, a0, o);
        a1 += __shfl_down_sync(0xffffffffu, a1, o);
        a2 += __shfl_down_sync(0xffffffffu, a2, o);
    }
    if (lane == 0) {
        out[(size_t)node * 3 + 0] = a0 + bc[0];
        out[(size_t)node * 3 + 1] = a1 + bc[1];
        out[(size_t)node * 3 + 2] = a2 + bc[2];
    }
}

// ---------------- launch -----------------------------------------------------
extern "C" void kernel_launch(void* const* d_in, const int* in_sizes, int n_in,
                              void* d_out, int out_size) {
    const float* x  = (const float*)d_in[0];
    const void*  ei = d_in[1];
    const float* W1 = (const float*)d_in[2];
    const float* b1 = (const float*)d_in[3];
    const float* W2 = (const float*)d_in[4];
    const float* b2 = (const float*)d_in[5];
    const float* W3 = (const float*)d_in[6];
    const float* b3 = (const float*)d_in[7];
    const float* Wi = (const float*)d_in[8];
    const float* bi = (const float*)d_in[9];
    const float* Wc = (const float*)d_in[10];
    const float* bc = (const float*)d_in[11];
    float* out = (float*)d_out;

    // buffer ids: 0 = g_bufA, 1 = g_bufB, 2 = g_h3, 3 = g_h4 (all half)
    const int NB_NODE = (N_NODES + 255) / 256;
    const int NB_EDGE = (N_EDGES + 255) / 256;
    const int NB_AGG  = (N_NODES + 7) / 8;
    const dim3 GRID_128(1, (N_NODES + 127) / 128);
    const dim3 GRID_512(4, (N_NODES + 127) / 128);

    // graph structure
    k_detect<<<1, 256>>>(ei);
    k_init<<<NB_NODE, 256>>>();
    k_count<<<NB_EDGE, 256>>>(ei);
    k_dinv<<<NB_NODE, 256>>>();
    k_scan<<<1, 1024>>>();
    k_fill<<<NB_EDGE, 256>>>(ei);

    // one-time conversions
    k_cvt<<<(N_NODES * 128 / 4 + 255) / 256, 256>>>(x);        // x -> half in buf3
    k_wt<<<(128 * 128 + 255) / 256, 256>>>(W1, 128, 128, WOFF_W1);
    k_wt<<<(128 * 128 + 255) / 256, 256>>>(W2, 128, 128, WOFF_W2);
    k_wt<<<(128 * 512 + 255) / 256, 256>>>(W3, 128, 512, WOFF_W3);
    k_wt<<<(512 * 512 + 255) / 256, 256>>>(Wi, 512, 512, WOFF_WI);

    // conv1: h1 = relu(Â(x@W1) + b1)
    k_hgemm<false, false><<<GRID_128, 256>>>(N_NODES, 128, 128, 3, WOFF_W1, nullptr, 0);
    k_aggregate<true, true><<<NB_AGG, 256>>>(0, 1, b1);

    // conv2: h2 = relu(Â(h1@W2) + b2)
    k_hgemm<false, false><<<GRID_128, 256>>>(N_NODES, 128, 128, 1, WOFF_W2, nullptr, 0);
    k_aggregate<true, true><<<NB_AGG, 256>>>(0, 1, b2);

    // conv3: h3 = relu((Âh2)@W3 + b3)  -- aggregate at 128-dim, then expand
    k_aggregate<false, false><<<NB_AGG, 256>>>(1, 0, nullptr);
    k_hgemm<true, true><<<GRID_512, 256>>>(N_NODES, 512, 128, 0, WOFF_W3, b3, 2);

    // MLP: h4 = relu(h3@Wi + bi); out = h4@Wc + bc
    k_hgemm<true, true><<<GRID_512, 256>>>(N_NODES, 512, 512, 2, WOFF_WI, bi, 3);
    k_final<<<NB_AGG, 256>>>(Wc, bc, out);
}